// round 14
// baseline (speedup 1.0000x reference)
#include <cuda_runtime.h>
#include <math.h>
#include <stdint.h>

// ---------------------------------------------------------------------------
// BidirectionalAttentionalPromptEncoder — batch-invariant (B=1) formulation.
// R14 = R13 + LSTM dot in packed fma.rn.f32x2 (2 k-elems per op, no packing
// MOVs; 4 independent acc chains) + Y store moved off the release path.
// ---------------------------------------------------------------------------

// ----------------------------- scratch --------------------------------------
#define OFF_X    0          // [4][64][1024]
#define OFF_Y0   1310720    // [4][64][1024]
#define OFF_Y1   1572864    // [4][64][1024]
#define OFF_HB   1835008    // [2][8][512]
#define OFF_GH2  2240512    // [2][64][1024]
#define OFF_BI   2633728    // [2][64][1024]
#define OFF_AO   3158016
#define OFF_LNO  3420160
#define OFF_T2   3813376    // [2][64][2048]
#define OFF_PART 4337664    // split-K partials
#define SCRATCH_TOTAL 6434816

__device__ float g_scratch[SCRATCH_TOTAL];

// per-group barrier counters; monotonic within a launch, zeroed by embed_kernel.
__device__ unsigned g_grp_cnt[4 * 32];

__device__ __forceinline__ float sigf(float x) { return 1.0f / (1.0f + expf(-x)); }

__device__ __forceinline__ float sig_fast(float x) {
    return 1.0f / (1.0f + __expf(-x));
}
__device__ __forceinline__ float tanh_fast(float x) {
    float e = __expf(2.0f * x);
    return 1.0f - 2.0f / (e + 1.0f);
}

__device__ __forceinline__ void bar_red_release(unsigned* cnt) {
    asm volatile("red.release.gpu.global.add.u32 [%0], %1;"
                 :: "l"(cnt), "r"(1u) : "memory");
}
__device__ __forceinline__ unsigned ld_acquire(unsigned* p) {
    unsigned v;
    asm volatile("ld.acquire.gpu.global.u32 %0, [%1];"
                 : "=r"(v) : "l"(p) : "memory");
    return v;
}
__device__ __forceinline__ uint32_t f2tf32(float x) {
    uint32_t r; asm("cvt.rna.tf32.f32 %0, %1;" : "=r"(r) : "f"(x)); return r;
}
__device__ __forceinline__ void cpasync16(void* dst, const void* src) {
    uint32_t d = (uint32_t)__cvta_generic_to_shared(dst);
    asm volatile("cp.async.ca.shared.global [%0], [%1], 16;" :: "r"(d), "l"(src));
}
// packed f32x2 fma: acc(lane0,lane1) += a * w, per-lane IEEE fma
__device__ __forceinline__ void fma2(unsigned long long& acc,
                                     unsigned long long a,
                                     unsigned long long w) {
    asm("fma.rn.f32x2 %0, %1, %2, %0;" : "+l"(acc) : "l"(a), "l"(w));
}
__device__ __forceinline__ float hsum2(unsigned long long v) {
    float lo, hi;
    asm("mov.b64 {%0,%1}, %2;" : "=f"(lo), "=f"(hi) : "l"(v));
    return lo + hi;
}

// ----------------------------- embedding ------------------------------------
__global__ void embed_kernel(const float* __restrict__ pre,
                             const float* __restrict__ suf) {
    if (blockIdx.x == 0 && threadIdx.x < 128) g_grp_cnt[threadIdx.x] = 0;
    int idx = blockIdx.x * 256 + threadIdx.x;   // < 4*64*1024
    int b = idx >> 16;
    int t = (idx >> 10) & 63;
    int c = idx & 1023;
    int st = (b >= 2) ? (63 - t) : t;
    const float* e = (b & 1) ? suf : pre;
    int i2 = c & ~1;
    const float LOG2_10000 = 13.28771237954945f;
    float divf = exp2f(-LOG2_10000 * (float)i2 * (1.0f / 1024.0f));
    double ang = (double)st * (double)divf;
    const double TWO_PI = 6.283185307179586476925286766559;
    double red = ang - floor(ang * (1.0 / TWO_PI)) * TWO_PI;
    float rf = (float)red;
    float pe = (c & 1) ? cosf(rf) : sinf(rf);
    g_scratch[OFF_X + idx] = e[st * 1024 + c] + pe;
}

// --------------------------- tf32 tensor GEMM (pipelined) -------------------
struct GemmSK {
    const float* A[8];
    const float* A2[8];
    const float* W[8];
};

#define GSTAGES 4
#define GSM_A  (64 * 20)
#define GSM_W  (128 * 20)
#define GSM_TOTAL ((GSTAGES * (GSM_A + GSM_W)) * 4)   // 61440 bytes

__global__ void __launch_bounds__(256, 2) gemm_tc(GemmSK p, float* part,
                                                  int N, int K, int chunkK,
                                                  int gather) {
    extern __shared__ float gsm[];
    float* As = gsm;
    float* Ws = gsm + GSTAGES * GSM_A;
    int bz = blockIdx.y, kc = blockIdx.z;
    const float* A  = p.A[bz];
    const float* A2 = p.A2[bz];
    const float* W  = p.W[bz];
    int n0 = blockIdx.x * 128;
    int tid = threadIdx.x;
    int warp = tid >> 5, lane = tid & 31;
    int mt = warp & 3, nh = warp >> 2;
    int gid = lane >> 2, tig = lane & 3;

    int am = tid >> 2, akq = (tid & 3) * 4;
    int wn0 = (tid * 2) >> 2, wkq0 = ((tid * 2) & 3) * 4;
    int wn1 = (tid * 2 + 1) >> 2, wkq1 = ((tid * 2 + 1) & 3) * 4;

    float c[8][4];
#pragma unroll
    for (int i = 0; i < 8; i++)
#pragma unroll
        for (int j = 0; j < 4; j++) c[i][j] = 0.0f;

    int kbeg = kc * chunkK;
    int niter = chunkK >> 4;

#define G_LOAD(K0, S)                                                          \
    do {                                                                       \
        int k0_ = (K0);                                                        \
        const float* asrc_;                                                    \
        if (gather) {                                                          \
            if (k0_ < 1024) asrc_ = A  + (size_t)am * 1024 + k0_ + akq;        \
            else            asrc_ = A2 + (size_t)(63 - am) * 1024 + (k0_ - 1024) + akq; \
        } else {                                                               \
            asrc_ = A + (size_t)am * K + k0_ + akq;                            \
        }                                                                      \
        cpasync16(As + ((S) * 64 + am) * 20 + akq, asrc_);                     \
        cpasync16(Ws + ((S) * 128 + wn0) * 20 + wkq0,                          \
                  W + (size_t)(n0 + wn0) * K + k0_ + wkq0);                    \
        cpasync16(Ws + ((S) * 128 + wn1) * 20 + wkq1,                          \
                  W + (size_t)(n0 + wn1) * K + k0_ + wkq1);                    \
    } while (0)

#pragma unroll
    for (int s = 0; s < GSTAGES - 1; s++) {
        if (s < niter) G_LOAD(kbeg + s * 16, s);
        asm volatile("cp.async.commit_group;");
    }

    for (int i = 0; i < niter; i++) {
        asm volatile("cp.async.wait_group 2;");
        __syncthreads();
        int nx = i + GSTAGES - 1;
        if (nx < niter) G_LOAD(kbeg + nx * 16, nx & (GSTAGES - 1));
        asm volatile("cp.async.commit_group;");

        int buf = i & (GSTAGES - 1);
        const float* Ab = As + buf * GSM_A;
        const float* Wb = Ws + buf * GSM_W;
#pragma unroll
        for (int ks = 0; ks < 2; ks++) {
            int kb = ks * 8;
            uint32_t a0 = f2tf32(Ab[(mt * 16 + gid) * 20 + kb + tig]);
            uint32_t a1 = f2tf32(Ab[(mt * 16 + gid + 8) * 20 + kb + tig]);
            uint32_t a2 = f2tf32(Ab[(mt * 16 + gid) * 20 + kb + tig + 4]);
            uint32_t a3 = f2tf32(Ab[(mt * 16 + gid + 8) * 20 + kb + tig + 4]);
#pragma unroll
            for (int nf = 0; nf < 8; nf++) {
                uint32_t b0 = f2tf32(Wb[(nh * 64 + nf * 8 + gid) * 20 + kb + tig]);
                uint32_t b1 = f2tf32(Wb[(nh * 64 + nf * 8 + gid) * 20 + kb + tig + 4]);
                asm volatile(
                    "mma.sync.aligned.m16n8k8.row.col.f32.tf32.tf32.f32 "
                    "{%0,%1,%2,%3}, {%4,%5,%6,%7}, {%8,%9}, {%0,%1,%2,%3};"
                    : "+f"(c[nf][0]), "+f"(c[nf][1]), "+f"(c[nf][2]), "+f"(c[nf][3])
                    : "r"(a0), "r"(a1), "r"(a2), "r"(a3), "r"(b0), "r"(b1));
            }
        }
    }
#undef G_LOAD

    float* outp = part + (size_t)(kc * gridDim.y + bz) * 64 * N;
    int m0 = mt * 16 + gid;
    int nb = n0 + nh * 64 + tig * 2;
#pragma unroll
    for (int nf = 0; nf < 8; nf++) {
        int n = nb + nf * 8;
        *(float2*)(outp + (size_t)m0 * N + n)       = make_float2(c[nf][0], c[nf][1]);
        *(float2*)(outp + (size_t)(m0 + 8) * N + n) = make_float2(c[nf][2], c[nf][3]);
    }
}

// --------------- fused split-K reduce + bias + LN(+gelu)(+add)(+bcast) ------
__global__ void __launch_bounds__(256) reduce_ln(
    const float* __restrict__ part, const float* __restrict__ bias, int bstride,
    const float* __restrict__ addrow,
    const float* __restrict__ gamma, const float* __restrict__ beta,
    float* __restrict__ out, int N, int KS, int dogelu, int perhalf,
    int bcast) {
    int row = blockIdx.x;
    int bz = row >> 6, m = row & 63;
    int tid = threadIdx.x;
    int nch = N >> 8;
    const float* prow = part + ((size_t)bz * 64 + m) * N;
    size_t stride = (size_t)2 * 64 * N;
    float v[8];
    float s = 0.f;
    for (int c = 0; c < nch; c++) {
        int i = c * 256 + tid;
        float acc = bias[bz * bstride + i];
        for (int ks = 0; ks < KS; ks++) acc += prow[(size_t)ks * stride + i];
        if (addrow) acc += addrow[(size_t)row * N + i];
        v[c] = acc; s += acc;
    }
    __shared__ float red[256];
    red[tid] = s; __syncthreads();
    for (int o = 128; o > 0; o >>= 1) { if (tid < o) red[tid] += red[tid + o]; __syncthreads(); }
    float mean = red[0] / N;
    __syncthreads();
    float v2 = 0.f;
    for (int c = 0; c < nch; c++) { float d = v[c] - mean; v2 += d * d; }
    red[tid] = v2; __syncthreads();
    for (int o = 128; o > 0; o >>= 1) { if (tid < o) red[tid] += red[tid + o]; __syncthreads(); }
    float inv = rsqrtf(red[0] / N + 1e-5f);
    int goff = perhalf ? bz * N : 0;
    for (int c = 0; c < nch; c++) {
        int i = c * 256 + tid;
        float o2 = (v[c] - mean) * inv * gamma[goff + i] + beta[goff + i];
        if (dogelu) o2 = 0.5f * o2 * (1.0f + erff(o2 * 0.70710678118654752f));
        if (bcast) {
            size_t basep = ((size_t)bz * bcast) * 65536 + (size_t)m * 1024 + i;
            for (int b = 0; b < bcast; b++)
                out[basep + (size_t)b * 65536] = o2;
        } else {
            out[(size_t)row * N + i] = o2;
        }
    }
}

// ------------- fused split-K reduce + bias + sigmoid gate combine -----------
__global__ void reduce_combine(const float* __restrict__ part,
                               const float* __restrict__ gate_b2, int KS) {
    int idx = blockIdx.x * 256 + threadIdx.x;   // < 2*64*1024
    int i = idx >> 16;
    int t = (idx >> 10) & 63;
    int c = idx & 1023;
    const float* prow = part + ((size_t)i * 64 + t) * 2048;
    size_t stride = (size_t)2 * 64 * 2048;
    float fs = gate_b2[i * 2048 + c];
    float bs = gate_b2[i * 2048 + 1024 + c];
    for (int ks = 0; ks < KS; ks++) {
        fs += prow[(size_t)ks * stride + c];
        bs += prow[(size_t)ks * stride + 1024 + c];
    }
    const float* Y1 = g_scratch + OFF_Y1;
    float f = Y1[(size_t)(i * 64 + t) * 1024 + c];
    float b = Y1[(size_t)((i + 2) * 64 + (63 - t)) * 1024 + c];
    g_scratch[OFF_BI + idx] = sigf(fs) * f + sigf(bs) * b;
}

// ------------------------ persistent LSTM layer ------------------------------
// 128 CTAs (1/SM). Weights + XZ slice in SMEM; lower K-half of weights in
// registers. Dot uses packed fma.rn.f32x2 (2 k-elems per op). Step sync:
// warp0 gates/stores h/releases; warp1 polls concurrently; Y stored after
// the release (off the inter-CTA critical path).
__global__ void __launch_bounds__(256, 1) lstm_persistent(
    const float* __restrict__ Whh, const float* __restrict__ part,
    const float* __restrict__ bih, const float* __restrict__ bhh, int layer) {
    extern __shared__ float smem[];
    float* sw  = smem;                 // [64][516] weight rows
    float* xzs = smem + 64 * 516;      // [2][64][64]

    float* Hb = g_scratch + OFF_HB;
    float* Y  = g_scratch + (layer == 0 ? OFF_Y0 : OFF_Y1);

    int blk = blockIdx.x;
    int g = blk >> 5;                  // lstm*2+dir
    int chunk = blk & 31;
    int lstm = g >> 1, dir = g & 1;
    int scanA = lstm * 4 + dir;
    int scanB = lstm * 4 + 2 + dir;
    int u0 = chunk * 16;
    int wi = (lstm * 2 + layer) * 2 + dir;
    const float* Wg   = Whh + (size_t)wi * (2048 * 512);
    const float* bihg = bih + (size_t)wi * 2048;
    const float* bhhg = bhh + (size_t)wi * 2048;
    int tid = threadIdx.x;
    unsigned* cnt = &g_grp_cnt[g * 32];
    unsigned base = (unsigned)layer * 2048u;

    for (int i4 = tid; i4 < 8192; i4 += 256) {
        int r = i4 >> 7, c4 = i4 & 127;
        int grow = (r >> 4) * 512 + u0 + (r & 15);
        float4 v = *(const float4*)(Wg + (size_t)grow * 512 + c4 * 4);
        *(float4*)(sw + r * 516 + c4 * 4) = v;
    }
    for (int i = tid; i < 8192; i += 256) {
        int sB = i >> 12, t = (i >> 6) & 63, r = i & 63;
        int scan = sB ? scanB : scanA;
        int row = (r >> 4) * 512 + u0 + (r & 15);
        size_t e0 = ((size_t)(0 * 8 + scan) * 64 + t) * 2048 + row;
        size_t e1 = ((size_t)(1 * 8 + scan) * 64 + t) * 2048 + row;
        xzs[i] = part[e0] + part[e1] + bihg[row] + bhhg[row];
    }
    if (tid < 32) {
        int sB = tid >> 4, uu = tid & 15;
        int scan = sB ? scanB : scanA;
        Hb[scan * 512 + u0 + uu] = 0.f;
    }
    __syncthreads();
    if (tid == 0) bar_red_release(cnt);
    if (tid == 32) {
        unsigned tgt = base + 32u;
        while (ld_acquire(cnt) < tgt) {}
    }
    __syncthreads();

    __shared__ __align__(16) float hA[512], hB[512];
    __shared__ float part_s[2][4][64];

    // preload h for step 0
    {
        int q = tid & 127;
        const float* src = Hb + (tid < 128 ? scanA : scanB) * 512;
        float4 v = __ldcg((const float4*)src + q);
        float* dst = (tid < 128) ? hA : hB;
        *(float4*)(dst + q * 4) = v;
    }
    __syncthreads();

    int r = tid & 63, pp = tid >> 6;
    // register-cache the lower K-half of this thread's weight slice as
    // ulonglong2 (each = one float4 = two packed f32x2 operands)
    ulonglong2 wreg[16];
    {
        const ulonglong2* wsrc = (const ulonglong2*)(sw + r * 516 + pp * 128);
#pragma unroll
        for (int k = 0; k < 16; k++) wreg[k] = wsrc[k];
    }
    const ulonglong2* wr2 = (const ulonglong2*)(sw + r * 516 + pp * 128);

    float cstate = 0.f;
    int mySB = tid >> 4, myU = tid & 15;
    int myScan = mySB ? scanB : scanA;

    for (int j = 0; j < 64; j++) {
        int t = dir ? (63 - j) : j;
        {
            const ulonglong2* a2 = (const ulonglong2*)(hA + pp * 128);
            const ulonglong2* b2 = (const ulonglong2*)(hB + pp * 128);
            unsigned long long aA0 = 0ull, aA1 = 0ull, aB0 = 0ull, aB1 = 0ull;
#pragma unroll
            for (int i = 0; i < 16; i++) {          // register half (k 0..63)
                ulonglong2 w = wreg[i];
                ulonglong2 a = a2[i], b = b2[i];
                fma2(aA0, a.x, w.x);
                fma2(aB0, b.x, w.x);
                fma2(aA1, a.y, w.y);
                fma2(aB1, b.y, w.y);
            }
#pragma unroll
            for (int i = 16; i < 32; i++) {         // smem half (k 64..127)
                ulonglong2 w = wr2[i];
                ulonglong2 a = a2[i], b = b2[i];
                fma2(aA0, a.x, w.x);
                fma2(aB0, b.x, w.x);
                fma2(aA1, a.y, w.y);
                fma2(aB1, b.y, w.y);
            }
            part_s[0][pp][r] = hsum2(aA0) + hsum2(aA1);
            part_s[1][pp][r] = hsum2(aB0) + hsum2(aB1);
        }
        __syncthreads();
        float* Hnext = Hb + ((j + 1) & 1) * 4096;
        if (tid < 32) {
            float z[4];
#pragma unroll
            for (int gg = 0; gg < 4; gg++) {
                int rr = gg * 16 + myU;
                z[gg] = xzs[mySB * 4096 + t * 64 + rr]
                      + part_s[mySB][0][rr] + part_s[mySB][1][rr]
                      + part_s[mySB][2][rr] + part_s[mySB][3][rr];
            }
            float c = sig_fast(z[1]) * cstate + sig_fast(z[0]) * tanh_fast(z[2]);
            float h = sig_fast(z[3]) * tanh_fast(c);
            cstate = c;
            Hnext[myScan * 512 + u0 + myU] = h;
            __syncwarp(0xffffffffu);               // order warp0's h STGs
            if (tid == 0 && j < 63) bar_red_release(cnt);
            // Y store off the critical path (consumed only after kernel end)
            int seq = lstm * 2 + mySB;
            Y[(size_t)(seq * 64 + t) * 1024 + dir * 512 + u0 + myU] = h;
        } else if (tid == 32 && j < 63) {
            unsigned tgt = base + (unsigned)(j + 2) * 32u;
            while (ld_acquire(cnt) < tgt) {}
        }
        if (j == 63) break;
        __syncthreads();
        {
            const float* Hp = Hb + ((j + 1) & 1) * 4096;
            int q = tid & 127;
            const float* src = Hp + (tid < 128 ? scanA : scanB) * 512;
            float4 v = __ldcg((const float4*)src + q);
            float* dst = (tid < 128) ? hA : hB;
            *(float4*)(dst + q * 4) = v;
        }
        __syncthreads();
    }
}

// ----------------------------- attention core -------------------------------
__global__ void __launch_bounds__(256) attn_core_kernel(
    const float* __restrict__ part, const float* __restrict__ attn_b) {
    extern __shared__ float asm_[];
    float* KV  = asm_;            // [64][128]
    float* Qs  = asm_ + 8192;     // [64][128]
    float* Ssm = asm_ + 16384;    // [64][64]
    const int h = blockIdx.x;
    const int a = blockIdx.y;
    float* AO = g_scratch + OFF_AO + (size_t)a * 64 * 1024;
    int tid = threadIdx.x;

    for (int i = tid; i < 64 * 128; i += 256) {
        int m = i >> 7, d = i & 127;
        int col = h * 128 + d;
        int eq = a * 3 + 0, ek = a * 3 + 1;
        float q = 0.f, k = 0.f;
#pragma unroll
        for (int ks = 0; ks < 4; ks++) {
            q += part[((size_t)(ks * 6 + eq) * 64 + m) * 1024 + col];
            k += part[((size_t)(ks * 6 + ek) * 64 + m) * 1024 + col];
        }
        q += attn_b[(a * 4 + 0) * 1024 + col];
        k += attn_b[(a * 4 + 1) * 1024 + col];
        Qs[m * 128 + d] = q;
        KV[m * 128 + d] = k;
    }
    __syncthreads();
    {
        int n = tid >> 2, p = tid & 3;
        float acc[16];
#pragma unroll
        for (int i = 0; i < 16; i++) acc[i] = 0.f;
        const float* q = Qs + n * 128;
        for (int d = 0; d < 128; d++) {
            float qv = q[d];
#pragma unroll
            for (int i = 0; i < 16; i++) acc[i] += qv * KV[(p * 16 + i) * 128 + d];
        }
        const float scale = 0.08838834764831845f;
#pragma unroll
        for (int i = 0; i < 16; i++) Ssm[n * 64 + p * 16 + i] = acc[i] * scale;
    }
    __syncthreads();
    for (int i = tid; i < 64 * 128; i += 256) {
        int m = i >> 7, d = i & 127;
        int col = h * 128 + d;
        int ev = a * 3 + 2;
        float v = 0.f;
#pragma unroll
        for (int ks = 0; ks < 4; ks++)
            v += part[((size_t)(ks * 6 + ev) * 64 + m) * 1024 + col];
        v += attn_b[(a * 4 + 2) * 1024 + col];
        KV[m * 128 + d] = v;
    }
    if (tid < 64) {
        float mx = -1e30f;
        for (int m = 0; m < 64; m++) mx = fmaxf(mx, Ssm[tid * 64 + m]);
        float sum = 0.f;
        for (int m = 0; m < 64; m++) {
            float e = expf(Ssm[tid * 64 + m] - mx);
            Ssm[tid * 64 + m] = e; sum += e;
        }
        float invs = 1.f / sum;
        for (int m = 0; m < 64; m++) Ssm[tid * 64 + m] *= invs;
    }
    __syncthreads();
    {
        int n = tid >> 2, p = tid & 3;
        float acc[32];
#pragma unroll
        for (int i = 0; i < 32; i++) acc[i] = 0.f;
        for (int m = 0; m < 64; m++) {
            float w = Ssm[n * 64 + m];
#pragma unroll
            for (int i = 0; i < 32; i++) acc[i] += w * KV[m * 128 + p * 32 + i];
        }
        for (int i = 0; i < 32; i++)
            AO[n * 1024 + h * 128 + p * 32 + i] = acc[i];
    }
}

// ------------------------------- launcher -----------------------------------
extern "C" void kernel_launch(void* const* d_in, const int* in_sizes, int n_in,
                              void* d_out, int out_size) {
    const float* prefix  = (const float*)d_in[0];
    const float* suffix  = (const float*)d_in[1];
    const float* Wih     = (const float*)d_in[2];
    const float* Whh     = (const float*)d_in[3];
    const float* bih     = (const float*)d_in[4];
    const float* bhh     = (const float*)d_in[5];
    const float* attn_w  = (const float*)d_in[6];
    const float* attn_b  = (const float*)d_in[7];
    const float* gate_w1 = (const float*)d_in[8];
    const float* gate_b1 = (const float*)d_in[9];
    const float* gate_lg = (const float*)d_in[10];
    const float* gate_lb = (const float*)d_in[11];
    const float* gate_w2 = (const float*)d_in[12];
    const float* gate_b2 = (const float*)d_in[13];
    const float* out_w1  = (const float*)d_in[14];
    const float* out_b1  = (const float*)d_in[15];
    const float* out_g1  = (const float*)d_in[16];
    const float* out_be1 = (const float*)d_in[17];
    const float* out_w2  = (const float*)d_in[18];
    const float* out_b2  = (const float*)d_in[19];
    const float* out_g2  = (const float*)d_in[20];
    const float* out_be2 = (const float*)d_in[21];
    const float* ln_g    = (const float*)d_in[22];
    const float* ln_b    = (const float*)d_in[23];
    float* out = (float*)d_out;

    float* S = nullptr;
    cudaGetSymbolAddress((void**)&S, g_scratch);
    float* X    = S + OFF_X;
    float* Y0   = S + OFF_Y0;
    float* Y1   = S + OFF_Y1;
    float* GH2  = S + OFF_GH2;
    float* BI   = S + OFF_BI;
    float* AO   = S + OFF_AO;
    float* LNO  = S + OFF_LNO;
    float* T2   = S + OFF_T2;
    float* PART = S + OFF_PART;

    const int LSTM_SMEM = (64 * 516 + 8192) * 4;
    const int ATTN_SMEM = (8192 + 8192 + 4096) * 4;
    static int smem_set = 0;
    if (!smem_set) {
        cudaFuncSetAttribute(lstm_persistent,
                             cudaFuncAttributeMaxDynamicSharedMemorySize, LSTM_SMEM);
        cudaFuncSetAttribute(gemm_tc,
                             cudaFuncAttributeMaxDynamicSharedMemorySize, GSM_TOTAL);
        cudaFuncSetAttribute(attn_core_kernel,
                             cudaFuncAttributeMaxDynamicSharedMemorySize, ATTN_SMEM);
        smem_set = 1;
    }

    int nbatch = (out_size / 2) / 65536;   // 64

    // 1) embed + PE (zeroes barrier counters)
    embed_kernel<<<1024, 256>>>(prefix, suffix);

    // 2) bilstm: XZ gemm (split-K, KS=2) -> persistent LSTM (reduce fused in)
    for (int layer = 0; layer < 2; layer++) {
        const float* src = (layer == 0) ? X : Y0;
        GemmSK gs;
        for (int s = 0; s < 8; s++) {
            int seq = s >> 1, dir = s & 1, lstm = seq >> 1;
            int wi = (lstm * 2 + layer) * 2 + dir;
            gs.A[s]  = src + (size_t)seq * 64 * 1024;
            gs.A2[s] = nullptr;
            gs.W[s]  = Wih + (size_t)wi * 2048 * 1024;
        }
        gemm_tc<<<dim3(16, 8, 2), 256, GSM_TOTAL>>>(gs, PART, 2048, 1024, 512, 0);
        lstm_persistent<<<128, 256, LSTM_SMEM>>>(Whh, PART, bih, bhh, layer);
    }

    // 3) gates: GEMM1 gathers concat(Y1[i], flip(Y1[i+2])) directly; KS=8
    {
        GemmSK gs;
        for (int i = 0; i < 2; i++) {
            gs.A[i]  = Y1 + (size_t)i * 64 * 1024;
            gs.A2[i] = Y1 + (size_t)(i + 2) * 64 * 1024;
            gs.W[i]  = gate_w1 + (size_t)i * 1024 * 2048;
        }
        gemm_tc<<<dim3(8, 2, 8), 256, GSM_TOTAL>>>(gs, PART, 1024, 2048, 256, 1);
        reduce_ln<<<128, 256>>>(PART, gate_b1, 1024, nullptr,
                                gate_lg, gate_lb, GH2, 1024, 8, 1, 1, 0);
    }
    {
        GemmSK gs;
        for (int i = 0; i < 2; i++) {
            gs.A[i]  = GH2 + (size_t)i * 64 * 1024;
            gs.A2[i] = nullptr;
            gs.W[i]  = gate_w2 + (size_t)i * 2048 * 1024;
        }
        gemm_tc<<<dim3(16, 2, 8), 256, GSM_TOTAL>>>(gs, PART, 2048, 1024, 128, 0);
        reduce_combine<<<512, 256>>>(PART, gate_b2, 8);
    }

    // 4) cross attention: QKV gemm (KS=4) -> fused attn core -> out proj
    {
        GemmSK gs;
        for (int a = 0; a < 2; a++)
            for (int k3 = 0; k3 < 3; k3++) {
                int e = a * 3 + k3;
                int srcIdx = (k3 == 0) ? a : (1 - a);
                gs.A[e]  = BI + (size_t)srcIdx * 64 * 1024;
                gs.A2[e] = nullptr;
                gs.W[e]  = attn_w + (size_t)(a * 4 + k3) * 1024 * 1024;
            }
        gemm_tc<<<dim3(8, 6, 4), 256, GSM_TOTAL>>>(gs, PART, 1024, 1024, 256, 0);
        attn_core_kernel<<<dim3(8, 2), 256, ATTN_SMEM>>>(PART, attn_b);
    }
    {
        GemmSK gs;
        for (int a = 0; a < 2; a++) {
            gs.A[a]  = AO + (size_t)a * 64 * 1024;
            gs.A2[a] = nullptr;
            gs.W[a]  = attn_w + (size_t)(a * 4 + 3) * 1024 * 1024;
        }
        gemm_tc<<<dim3(8, 2, 8), 256, GSM_TOTAL>>>(gs, PART, 1024, 1024, 128, 0);
        reduce_ln<<<128, 256>>>(PART, attn_b + 3 * 1024, 4096, BI,
                                ln_g, ln_b, LNO, 1024, 8, 0, 0, 0);
    }

    // 5) output transforms
    {
        GemmSK gs;
        for (int i = 0; i < 2; i++) {
            gs.A[i]  = LNO + (size_t)i * 64 * 1024;
            gs.A2[i] = nullptr;
            gs.W[i]  = out_w1 + (size_t)i * 2048 * 1024;
        }
        gemm_tc<<<dim3(16, 2, 8), 256, GSM_TOTAL>>>(gs, PART, 2048, 1024, 128, 0);
        reduce_ln<<<128, 256>>>(PART, out_b1, 2048, nullptr,
                                out_g1, out_be1, T2, 2048, 8, 1, 1, 0);
    }
    {
        GemmSK gs;
        for (int i = 0; i < 2; i++) {
            gs.A[i]  = T2 + (size_t)i * 64 * 2048;
            gs.A2[i] = nullptr;
            gs.W[i]  = out_w2 + (size_t)i * 1024 * 2048;
        }
        gemm_tc<<<dim3(8, 2, 8), 256, GSM_TOTAL>>>(gs, PART, 1024, 2048, 256, 0);
        reduce_ln<<<128, 256>>>(PART, out_b2, 1024, nullptr,
                                out_g2, out_be2, out, 1024, 8, 0, 1, nbatch);
    }
}

// round 15
// speedup vs baseline: 1.0272x; 1.0272x over previous
#include <cuda_runtime.h>
#include <math.h>
#include <stdint.h>

// ---------------------------------------------------------------------------
// BidirectionalAttentionalPromptEncoder — batch-invariant (B=1) formulation.
// R15 = R13 (LSTM reverted to best-known) + gemm_tc retiled: BK=32, 3-stage
// cp.async pipeline, warp tile 2 m-tiles x 4 n-frags (fewer fragment loads
// and half the loop overhead per MMA; identical per-element k-order => same
// numerics as R13).
// ---------------------------------------------------------------------------

// ----------------------------- scratch --------------------------------------
#define OFF_X    0          // [4][64][1024]
#define OFF_Y0   1310720    // [4][64][1024]
#define OFF_Y1   1572864    // [4][64][1024]
#define OFF_HB   1835008    // [2][8][512]
#define OFF_GH2  2240512    // [2][64][1024]
#define OFF_BI   2633728    // [2][64][1024]
#define OFF_AO   3158016
#define OFF_LNO  3420160
#define OFF_T2   3813376    // [2][64][2048]
#define OFF_PART 4337664    // split-K partials
#define SCRATCH_TOTAL 6434816

__device__ float g_scratch[SCRATCH_TOTAL];

// per-group barrier counters; monotonic within a launch, zeroed by embed_kernel.
__device__ unsigned g_grp_cnt[4 * 32];

__device__ __forceinline__ float sigf(float x) { return 1.0f / (1.0f + expf(-x)); }

__device__ __forceinline__ float sig_fast(float x) {
    return 1.0f / (1.0f + __expf(-x));
}
__device__ __forceinline__ float tanh_fast(float x) {
    float e = __expf(2.0f * x);
    return 1.0f - 2.0f / (e + 1.0f);
}

__device__ __forceinline__ void bar_red_release(unsigned* cnt) {
    asm volatile("red.release.gpu.global.add.u32 [%0], %1;"
                 :: "l"(cnt), "r"(1u) : "memory");
}
__device__ __forceinline__ unsigned ld_acquire(unsigned* p) {
    unsigned v;
    asm volatile("ld.acquire.gpu.global.u32 %0, [%1];"
                 : "=r"(v) : "l"(p) : "memory");
    return v;
}
__device__ __forceinline__ uint32_t f2tf32(float x) {
    uint32_t r; asm("cvt.rna.tf32.f32 %0, %1;" : "=r"(r) : "f"(x)); return r;
}
__device__ __forceinline__ void cpasync16(void* dst, const void* src) {
    uint32_t d = (uint32_t)__cvta_generic_to_shared(dst);
    asm volatile("cp.async.ca.shared.global [%0], [%1], 16;" :: "r"(d), "l"(src));
}

// ----------------------------- embedding ------------------------------------
__global__ void embed_kernel(const float* __restrict__ pre,
                             const float* __restrict__ suf) {
    if (blockIdx.x == 0 && threadIdx.x < 128) g_grp_cnt[threadIdx.x] = 0;
    int idx = blockIdx.x * 256 + threadIdx.x;   // < 4*64*1024
    int b = idx >> 16;
    int t = (idx >> 10) & 63;
    int c = idx & 1023;
    int st = (b >= 2) ? (63 - t) : t;
    const float* e = (b & 1) ? suf : pre;
    int i2 = c & ~1;
    const float LOG2_10000 = 13.28771237954945f;
    float divf = exp2f(-LOG2_10000 * (float)i2 * (1.0f / 1024.0f));
    double ang = (double)st * (double)divf;
    const double TWO_PI = 6.283185307179586476925286766559;
    double red = ang - floor(ang * (1.0 / TWO_PI)) * TWO_PI;
    float rf = (float)red;
    float pe = (c & 1) ? cosf(rf) : sinf(rf);
    g_scratch[OFF_X + idx] = e[st * 1024 + c] + pe;
}

// --------------------------- tf32 tensor GEMM (pipelined) -------------------
// partial[kc][bz] = A[64,K] · W[N,K]^T over K-chunk kc. Block tile 64x128,
// BK=32, 3-stage cp.async. Warps: (mw 0..1 [32 rows], nw 0..3 [32 cols]);
// per warp: 2 m16 tiles x 4 n8 frags, mma.m16n8k8 tf32.
struct GemmSK {
    const float* A[8];
    const float* A2[8];
    const float* W[8];
};

#define GSTAGES 3
#define GSM_A  (64 * 36)
#define GSM_W  (128 * 36)
#define GSM_TOTAL ((GSTAGES * (GSM_A + GSM_W)) * 4)   // 82944 bytes

__global__ void __launch_bounds__(256, 2) gemm_tc(GemmSK p, float* part,
                                                  int N, int K, int chunkK,
                                                  int gather) {
    extern __shared__ float gsm[];
    float* As = gsm;
    float* Ws = gsm + GSTAGES * GSM_A;
    int bz = blockIdx.y, kc = blockIdx.z;
    const float* A  = p.A[bz];
    const float* A2 = p.A2[bz];
    const float* W  = p.W[bz];
    int n0 = blockIdx.x * 128;
    int tid = threadIdx.x;
    int warp = tid >> 5, lane = tid & 31;
    int mw = warp & 1, nw = warp >> 1;       // mw: 32-row half, nw: 32-col quarter
    int gid = lane >> 2, tig = lane & 3;

    float c[2][4][4];
#pragma unroll
    for (int mt = 0; mt < 2; mt++)
#pragma unroll
        for (int nf = 0; nf < 4; nf++)
#pragma unroll
            for (int j = 0; j < 4; j++) c[mt][nf][j] = 0.0f;

    int kbeg = kc * chunkK;
    int niter = chunkK >> 5;

#define G_LOAD(K0, S)                                                          \
    do {                                                                       \
        int k0_ = (K0);                                                        \
        _Pragma("unroll")                                                      \
        for (int l = 0; l < 2; l++) {   /* A: 64x32 */                         \
            int ix = tid * 2 + l;                                              \
            int row = ix >> 3, kq = (ix & 7) * 4;                              \
            const float* asrc_;                                                \
            if (gather) {                                                      \
                if (k0_ < 1024) asrc_ = A  + (size_t)row * 1024 + k0_ + kq;    \
                else            asrc_ = A2 + (size_t)(63 - row) * 1024 + (k0_ - 1024) + kq; \
            } else {                                                           \
                asrc_ = A + (size_t)row * K + k0_ + kq;                        \
            }                                                                  \
            cpasync16(As + ((S) * 64 + row) * 36 + kq, asrc_);                 \
        }                                                                      \
        _Pragma("unroll")                                                      \
        for (int l = 0; l < 4; l++) {   /* W: 128x32 */                        \
            int ix = tid * 4 + l;                                              \
            int row = ix >> 3, kq = (ix & 7) * 4;                              \
            cpasync16(Ws + ((S) * 128 + row) * 36 + kq,                        \
                      W + (size_t)(n0 + row) * K + k0_ + kq);                  \
        }                                                                      \
    } while (0)

#pragma unroll
    for (int s = 0; s < GSTAGES - 1; s++) {
        if (s < niter) G_LOAD(kbeg + s * 32, s);
        asm volatile("cp.async.commit_group;");
    }

    for (int i = 0; i < niter; i++) {
        asm volatile("cp.async.wait_group 1;");
        __syncthreads();
        int nx = i + GSTAGES - 1;
        int nxbuf = nx % GSTAGES;
        if (nx < niter) G_LOAD(kbeg + nx * 32, nxbuf);
        asm volatile("cp.async.commit_group;");

        int buf = i % GSTAGES;
        const float* Ab = As + buf * GSM_A;
        const float* Wb = Ws + buf * GSM_W;
#pragma unroll
        for (int ks = 0; ks < 4; ks++) {
            int kb = ks * 8;
            uint32_t af[2][4];
#pragma unroll
            for (int mt = 0; mt < 2; mt++) {
                int m0 = mw * 32 + mt * 16;
                af[mt][0] = f2tf32(Ab[(m0 + gid) * 36 + kb + tig]);
                af[mt][1] = f2tf32(Ab[(m0 + gid + 8) * 36 + kb + tig]);
                af[mt][2] = f2tf32(Ab[(m0 + gid) * 36 + kb + tig + 4]);
                af[mt][3] = f2tf32(Ab[(m0 + gid + 8) * 36 + kb + tig + 4]);
            }
#pragma unroll
            for (int nf = 0; nf < 4; nf++) {
                int nrow = nw * 32 + nf * 8 + gid;
                uint32_t b0 = f2tf32(Wb[nrow * 36 + kb + tig]);
                uint32_t b1 = f2tf32(Wb[nrow * 36 + kb + tig + 4]);
#pragma unroll
                for (int mt = 0; mt < 2; mt++) {
                    asm volatile(
                        "mma.sync.aligned.m16n8k8.row.col.f32.tf32.tf32.f32 "
                        "{%0,%1,%2,%3}, {%4,%5,%6,%7}, {%8,%9}, {%0,%1,%2,%3};"
                        : "+f"(c[mt][nf][0]), "+f"(c[mt][nf][1]),
                          "+f"(c[mt][nf][2]), "+f"(c[mt][nf][3])
                        : "r"(af[mt][0]), "r"(af[mt][1]),
                          "r"(af[mt][2]), "r"(af[mt][3]), "r"(b0), "r"(b1));
                }
            }
        }
    }
#undef G_LOAD

    float* outp = part + (size_t)(kc * gridDim.y + bz) * 64 * N;
#pragma unroll
    for (int mt = 0; mt < 2; mt++) {
        int m0 = mw * 32 + mt * 16 + gid;
#pragma unroll
        for (int nf = 0; nf < 4; nf++) {
            int n = n0 + nw * 32 + nf * 8 + tig * 2;
            *(float2*)(outp + (size_t)m0 * N + n) =
                make_float2(c[mt][nf][0], c[mt][nf][1]);
            *(float2*)(outp + (size_t)(m0 + 8) * N + n) =
                make_float2(c[mt][nf][2], c[mt][nf][3]);
        }
    }
}

// --------------- fused split-K reduce + bias + LN(+gelu)(+add)(+bcast) ------
__global__ void __launch_bounds__(256) reduce_ln(
    const float* __restrict__ part, const float* __restrict__ bias, int bstride,
    const float* __restrict__ addrow,
    const float* __restrict__ gamma, const float* __restrict__ beta,
    float* __restrict__ out, int N, int KS, int dogelu, int perhalf,
    int bcast) {
    int row = blockIdx.x;
    int bz = row >> 6, m = row & 63;
    int tid = threadIdx.x;
    int nch = N >> 8;
    const float* prow = part + ((size_t)bz * 64 + m) * N;
    size_t stride = (size_t)2 * 64 * N;
    float v[8];
    float s = 0.f;
    for (int c = 0; c < nch; c++) {
        int i = c * 256 + tid;
        float acc = bias[bz * bstride + i];
        for (int ks = 0; ks < KS; ks++) acc += prow[(size_t)ks * stride + i];
        if (addrow) acc += addrow[(size_t)row * N + i];
        v[c] = acc; s += acc;
    }
    __shared__ float red[256];
    red[tid] = s; __syncthreads();
    for (int o = 128; o > 0; o >>= 1) { if (tid < o) red[tid] += red[tid + o]; __syncthreads(); }
    float mean = red[0] / N;
    __syncthreads();
    float v2 = 0.f;
    for (int c = 0; c < nch; c++) { float d = v[c] - mean; v2 += d * d; }
    red[tid] = v2; __syncthreads();
    for (int o = 128; o > 0; o >>= 1) { if (tid < o) red[tid] += red[tid + o]; __syncthreads(); }
    float inv = rsqrtf(red[0] / N + 1e-5f);
    int goff = perhalf ? bz * N : 0;
    for (int c = 0; c < nch; c++) {
        int i = c * 256 + tid;
        float o2 = (v[c] - mean) * inv * gamma[goff + i] + beta[goff + i];
        if (dogelu) o2 = 0.5f * o2 * (1.0f + erff(o2 * 0.70710678118654752f));
        if (bcast) {
            size_t basep = ((size_t)bz * bcast) * 65536 + (size_t)m * 1024 + i;
            for (int b = 0; b < bcast; b++)
                out[basep + (size_t)b * 65536] = o2;
        } else {
            out[(size_t)row * N + i] = o2;
        }
    }
}

// ------------- fused split-K reduce + bias + sigmoid gate combine -----------
__global__ void reduce_combine(const float* __restrict__ part,
                               const float* __restrict__ gate_b2, int KS) {
    int idx = blockIdx.x * 256 + threadIdx.x;   // < 2*64*1024
    int i = idx >> 16;
    int t = (idx >> 10) & 63;
    int c = idx & 1023;
    const float* prow = part + ((size_t)i * 64 + t) * 2048;
    size_t stride = (size_t)2 * 64 * 2048;
    float fs = gate_b2[i * 2048 + c];
    float bs = gate_b2[i * 2048 + 1024 + c];
    for (int ks = 0; ks < KS; ks++) {
        fs += prow[(size_t)ks * stride + c];
        bs += prow[(size_t)ks * stride + 1024 + c];
    }
    const float* Y1 = g_scratch + OFF_Y1;
    float f = Y1[(size_t)(i * 64 + t) * 1024 + c];
    float b = Y1[(size_t)((i + 2) * 64 + (63 - t)) * 1024 + c];
    g_scratch[OFF_BI + idx] = sigf(fs) * f + sigf(bs) * b;
}

// ------------------------ persistent LSTM layer (R13) ------------------------
__global__ void __launch_bounds__(256, 1) lstm_persistent(
    const float* __restrict__ Whh, const float* __restrict__ part,
    const float* __restrict__ bih, const float* __restrict__ bhh, int layer) {
    extern __shared__ float smem[];
    float* sw  = smem;                 // [64][516] weight rows
    float* xzs = smem + 64 * 516;      // [2][64][64]

    float* Hb = g_scratch + OFF_HB;
    float* Y  = g_scratch + (layer == 0 ? OFF_Y0 : OFF_Y1);

    int blk = blockIdx.x;
    int g = blk >> 5;                  // lstm*2+dir
    int chunk = blk & 31;
    int lstm = g >> 1, dir = g & 1;
    int scanA = lstm * 4 + dir;
    int scanB = lstm * 4 + 2 + dir;
    int u0 = chunk * 16;
    int wi = (lstm * 2 + layer) * 2 + dir;
    const float* Wg   = Whh + (size_t)wi * (2048 * 512);
    const float* bihg = bih + (size_t)wi * 2048;
    const float* bhhg = bhh + (size_t)wi * 2048;
    int tid = threadIdx.x;
    unsigned* cnt = &g_grp_cnt[g * 32];
    unsigned base = (unsigned)layer * 2048u;

    for (int i4 = tid; i4 < 8192; i4 += 256) {
        int r = i4 >> 7, c4 = i4 & 127;
        int grow = (r >> 4) * 512 + u0 + (r & 15);
        float4 v = *(const float4*)(Wg + (size_t)grow * 512 + c4 * 4);
        *(float4*)(sw + r * 516 + c4 * 4) = v;
    }
    for (int i = tid; i < 8192; i += 256) {
        int sB = i >> 12, t = (i >> 6) & 63, r = i & 63;
        int scan = sB ? scanB : scanA;
        int row = (r >> 4) * 512 + u0 + (r & 15);
        size_t e0 = ((size_t)(0 * 8 + scan) * 64 + t) * 2048 + row;
        size_t e1 = ((size_t)(1 * 8 + scan) * 64 + t) * 2048 + row;
        xzs[i] = part[e0] + part[e1] + bihg[row] + bhhg[row];
    }
    if (tid < 32) {
        int sB = tid >> 4, uu = tid & 15;
        int scan = sB ? scanB : scanA;
        Hb[scan * 512 + u0 + uu] = 0.f;
    }
    __syncthreads();
    if (tid == 0) bar_red_release(cnt);
    if (tid == 32) {
        unsigned tgt = base + 32u;
        while (ld_acquire(cnt) < tgt) {}
    }
    __syncthreads();

    __shared__ __align__(16) float hA[512], hB[512];
    __shared__ float part_s[2][4][64];

    // preload h for step 0
    {
        int q = tid & 127;
        const float* src = Hb + (tid < 128 ? scanA : scanB) * 512;
        float4 v = __ldcg((const float4*)src + q);
        float* dst = (tid < 128) ? hA : hB;
        *(float4*)(dst + q * 4) = v;
    }
    __syncthreads();

    int r = tid & 63, pp = tid >> 6;
    float4 wreg[16];
    {
        const float4* wsrc = (const float4*)(sw + r * 516 + pp * 128);
#pragma unroll
        for (int k = 0; k < 16; k++) wreg[k] = wsrc[k];
    }
    const float4* wr = (const float4*)(sw + r * 516 + pp * 128);

    float cstate = 0.f;
    int mySB = tid >> 4, myU = tid & 15;
    int myScan = mySB ? scanB : scanA;

    for (int j = 0; j < 64; j++) {
        int t = dir ? (63 - j) : j;
        {
            const float4* a4 = (const float4*)(hA + pp * 128);
            const float4* b4 = (const float4*)(hB + pp * 128);
            float accA = 0.f, accB = 0.f;
#pragma unroll
            for (int i = 0; i < 16; i++) {          // register half (k 0..63)
                float4 w = wreg[i], a = a4[i], b = b4[i];
                accA += w.x * a.x + w.y * a.y + w.z * a.z + w.w * a.w;
                accB += w.x * b.x + w.y * b.y + w.z * b.z + w.w * b.w;
            }
#pragma unroll
            for (int i = 16; i < 32; i++) {         // smem half (k 64..127)
                float4 w = wr[i], a = a4[i], b = b4[i];
                accA += w.x * a.x + w.y * a.y + w.z * a.z + w.w * a.w;
                accB += w.x * b.x + w.y * b.y + w.z * b.z + w.w * b.w;
            }
            part_s[0][pp][r] = accA;
            part_s[1][pp][r] = accB;
        }
        __syncthreads();
        float* Hnext = Hb + ((j + 1) & 1) * 4096;
        if (tid < 32) {
            float z[4];
#pragma unroll
            for (int gg = 0; gg < 4; gg++) {
                int rr = gg * 16 + myU;
                z[gg] = xzs[mySB * 4096 + t * 64 + rr]
                      + part_s[mySB][0][rr] + part_s[mySB][1][rr]
                      + part_s[mySB][2][rr] + part_s[mySB][3][rr];
            }
            float c = sig_fast(z[1]) * cstate + sig_fast(z[0]) * tanh_fast(z[2]);
            float h = sig_fast(z[3]) * tanh_fast(c);
            cstate = c;
            Hnext[myScan * 512 + u0 + myU] = h;
            int seq = lstm * 2 + mySB;
            Y[(size_t)(seq * 64 + t) * 1024 + dir * 512 + u0 + myU] = h;
            __syncwarp(0xffffffffu);               // order warp0's STGs
            if (tid == 0 && j < 63) bar_red_release(cnt);
        } else if (tid == 32 && j < 63) {
            unsigned tgt = base + (unsigned)(j + 2) * 32u;
            while (ld_acquire(cnt) < tgt) {}
        }
        if (j == 63) break;
        __syncthreads();
        {
            const float* Hp = Hb + ((j + 1) & 1) * 4096;
            int q = tid & 127;
            const float* src = Hp + (tid < 128 ? scanA : scanB) * 512;
            float4 v = __ldcg((const float4*)src + q);
            float* dst = (tid < 128) ? hA : hB;
            *(float4*)(dst + q * 4) = v;
        }
        __syncthreads();
    }
}

// ----------------------------- attention core -------------------------------
__global__ void __launch_bounds__(256) attn_core_kernel(
    const float* __restrict__ part, const float* __restrict__ attn_b) {
    extern __shared__ float asm_[];
    float* KV  = asm_;            // [64][128]
    float* Qs  = asm_ + 8192;     // [64][128]
    float* Ssm = asm_ + 16384;    // [64][64]
    const int h = blockIdx.x;
    const int a = blockIdx.y;
    float* AO = g_scratch + OFF_AO + (size_t)a * 64 * 1024;
    int tid = threadIdx.x;

    for (int i = tid; i < 64 * 128; i += 256) {
        int m = i >> 7, d = i & 127;
        int col = h * 128 + d;
        int eq = a * 3 + 0, ek = a * 3 + 1;
        float q = 0.f, k = 0.f;
#pragma unroll
        for (int ks = 0; ks < 4; ks++) {
            q += part[((size_t)(ks * 6 + eq) * 64 + m) * 1024 + col];
            k += part[((size_t)(ks * 6 + ek) * 64 + m) * 1024 + col];
        }
        q += attn_b[(a * 4 + 0) * 1024 + col];
        k += attn_b[(a * 4 + 1) * 1024 + col];
        Qs[m * 128 + d] = q;
        KV[m * 128 + d] = k;
    }
    __syncthreads();
    {
        int n = tid >> 2, p = tid & 3;
        float acc[16];
#pragma unroll
        for (int i = 0; i < 16; i++) acc[i] = 0.f;
        const float* q = Qs + n * 128;
        for (int d = 0; d < 128; d++) {
            float qv = q[d];
#pragma unroll
            for (int i = 0; i < 16; i++) acc[i] += qv * KV[(p * 16 + i) * 128 + d];
        }
        const float scale = 0.08838834764831845f;
#pragma unroll
        for (int i = 0; i < 16; i++) Ssm[n * 64 + p * 16 + i] = acc[i] * scale;
    }
    __syncthreads();
    for (int i = tid; i < 64 * 128; i += 256) {
        int m = i >> 7, d = i & 127;
        int col = h * 128 + d;
        int ev = a * 3 + 2;
        float v = 0.f;
#pragma unroll
        for (int ks = 0; ks < 4; ks++)
            v += part[((size_t)(ks * 6 + ev) * 64 + m) * 1024 + col];
        v += attn_b[(a * 4 + 2) * 1024 + col];
        KV[m * 128 + d] = v;
    }
    if (tid < 64) {
        float mx = -1e30f;
        for (int m = 0; m < 64; m++) mx = fmaxf(mx, Ssm[tid * 64 + m]);
        float sum = 0.f;
        for (int m = 0; m < 64; m++) {
            float e = expf(Ssm[tid * 64 + m] - mx);
            Ssm[tid * 64 + m] = e; sum += e;
        }
        float invs = 1.f / sum;
        for (int m = 0; m < 64; m++) Ssm[tid * 64 + m] *= invs;
    }
    __syncthreads();
    {
        int n = tid >> 2, p = tid & 3;
        float acc[32];
#pragma unroll
        for (int i = 0; i < 32; i++) acc[i] = 0.f;
        for (int m = 0; m < 64; m++) {
            float w = Ssm[n * 64 + m];
#pragma unroll
            for (int i = 0; i < 32; i++) acc[i] += w * KV[m * 128 + p * 32 + i];
        }
        for (int i = 0; i < 32; i++)
            AO[n * 1024 + h * 128 + p * 32 + i] = acc[i];
    }
}

// ------------------------------- launcher -----------------------------------
extern "C" void kernel_launch(void* const* d_in, const int* in_sizes, int n_in,
                              void* d_out, int out_size) {
    const float* prefix  = (const float*)d_in[0];
    const float* suffix  = (const float*)d_in[1];
    const float* Wih     = (const float*)d_in[2];
    const float* Whh     = (const float*)d_in[3];
    const float* bih     = (const float*)d_in[4];
    const float* bhh     = (const float*)d_in[5];
    const float* attn_w  = (const float*)d_in[6];
    const float* attn_b  = (const float*)d_in[7];
    const float* gate_w1 = (const float*)d_in[8];
    const float* gate_b1 = (const float*)d_in[9];
    const float* gate_lg = (const float*)d_in[10];
    const float* gate_lb = (const float*)d_in[11];
    const float* gate_w2 = (const float*)d_in[12];
    const float* gate_b2 = (const float*)d_in[13];
    const float* out_w1  = (const float*)d_in[14];
    const float* out_b1  = (const float*)d_in[15];
    const float* out_g1  = (const float*)d_in[16];
    const float* out_be1 = (const float*)d_in[17];
    const float* out_w2  = (const float*)d_in[18];
    const float* out_b2  = (const float*)d_in[19];
    const float* out_g2  = (const float*)d_in[20];
    const float* out_be2 = (const float*)d_in[21];
    const float* ln_g    = (const float*)d_in[22];
    const float* ln_b    = (const float*)d_in[23];
    float* out = (float*)d_out;

    float* S = nullptr;
    cudaGetSymbolAddress((void**)&S, g_scratch);
    float* X    = S + OFF_X;
    float* Y0   = S + OFF_Y0;
    float* Y1   = S + OFF_Y1;
    float* GH2  = S + OFF_GH2;
    float* BI   = S + OFF_BI;
    float* AO   = S + OFF_AO;
    float* LNO  = S + OFF_LNO;
    float* T2   = S + OFF_T2;
    float* PART = S + OFF_PART;

    const int LSTM_SMEM = (64 * 516 + 8192) * 4;
    const int ATTN_SMEM = (8192 + 8192 + 4096) * 4;
    static int smem_set = 0;
    if (!smem_set) {
        cudaFuncSetAttribute(lstm_persistent,
                             cudaFuncAttributeMaxDynamicSharedMemorySize, LSTM_SMEM);
        cudaFuncSetAttribute(gemm_tc,
                             cudaFuncAttributeMaxDynamicSharedMemorySize, GSM_TOTAL);
        cudaFuncSetAttribute(attn_core_kernel,
                             cudaFuncAttributeMaxDynamicSharedMemorySize, ATTN_SMEM);
        smem_set = 1;
    }

    int nbatch = (out_size / 2) / 65536;   // 64

    // 1) embed + PE (zeroes barrier counters)
    embed_kernel<<<1024, 256>>>(prefix, suffix);

    // 2) bilstm: XZ gemm (split-K, KS=2) -> persistent LSTM (reduce fused in)
    for (int layer = 0; layer < 2; layer++) {
        const float* src = (layer == 0) ? X : Y0;
        GemmSK gs;
        for (int s = 0; s < 8; s++) {
            int seq = s >> 1, dir = s & 1, lstm = seq >> 1;
            int wi = (lstm * 2 + layer) * 2 + dir;
            gs.A[s]  = src + (size_t)seq * 64 * 1024;
            gs.A2[s] = nullptr;
            gs.W[s]  = Wih + (size_t)wi * 2048 * 1024;
        }
        gemm_tc<<<dim3(16, 8, 2), 256, GSM_TOTAL>>>(gs, PART, 2048, 1024, 512, 0);
        lstm_persistent<<<128, 256, LSTM_SMEM>>>(Whh, PART, bih, bhh, layer);
    }

    // 3) gates: GEMM1 gathers concat(Y1[i], flip(Y1[i+2])) directly; KS=8
    {
        GemmSK gs;
        for (int i = 0; i < 2; i++) {
            gs.A[i]  = Y1 + (size_t)i * 64 * 1024;
            gs.A2[i] = Y1 + (size_t)(i + 2) * 64 * 1024;
            gs.W[i]  = gate_w1 + (size_t)i * 1024 * 2048;
        }
        gemm_tc<<<dim3(8, 2, 8), 256, GSM_TOTAL>>>(gs, PART, 1024, 2048, 256, 1);
        reduce_ln<<<128, 256>>>(PART, gate_b1, 1024, nullptr,
                                gate_lg, gate_lb, GH2, 1024, 8, 1, 1, 0);
    }
    {
        GemmSK gs;
        for (int i = 0; i < 2; i++) {
            gs.A[i]  = GH2 + (size_t)i * 64 * 1024;
            gs.A2[i] = nullptr;
            gs.W[i]  = gate_w2 + (size_t)i * 2048 * 1024;
        }
        gemm_tc<<<dim3(16, 2, 8), 256, GSM_TOTAL>>>(gs, PART, 2048, 1024, 128, 0);
        reduce_combine<<<512, 256>>>(PART, gate_b2, 8);
    }

    // 4) cross attention: QKV gemm (KS=4) -> fused attn core -> out proj
    {
        GemmSK gs;
        for (int a = 0; a < 2; a++)
            for (int k3 = 0; k3 < 3; k3++) {
                int e = a * 3 + k3;
                int srcIdx = (k3 == 0) ? a : (1 - a);
                gs.A[e]  = BI + (size_t)srcIdx * 64 * 1024;
                gs.A2[e] = nullptr;
                gs.W[e]  = attn_w + (size_t)(a * 4 + k3) * 1024 * 1024;
            }
        gemm_tc<<<dim3(8, 6, 4), 256, GSM_TOTAL>>>(gs, PART, 1024, 1024, 256, 0);
        attn_core_kernel<<<dim3(8, 2), 256, ATTN_SMEM>>>(PART, attn_b);
    }
    {
        GemmSK gs;
        for (int a = 0; a < 2; a++) {
            gs.A[a]  = AO + (size_t)a * 64 * 1024;
            gs.A2[a] = nullptr;
            gs.W[a]  = attn_w + (size_t)(a * 4 + 3) * 1024 * 1024;
        }
        gemm_tc<<<dim3(8, 2, 8), 256, GSM_TOTAL>>>(gs, PART, 1024, 1024, 128, 0);
        reduce_ln<<<128, 256>>>(PART, attn_b + 3 * 1024, 4096, BI,
                                ln_g, ln_b, LNO, 1024, 8, 0, 0, 0);
    }

    // 5) output transforms
    {
        GemmSK gs;
        for (int i = 0; i < 2; i++) {
            gs.A[i]  = LNO + (size_t)i * 64 * 1024;
            gs.A2[i] = nullptr;
            gs.W[i]  = out_w1 + (size_t)i * 2048 * 1024;
        }
        gemm_tc<<<dim3(16, 2, 8), 256, GSM_TOTAL>>>(gs, PART, 2048, 1024, 128, 0);
        reduce_ln<<<128, 256>>>(PART, out_b1, 2048, nullptr,
                                out_g1, out_be1, T2, 2048, 8, 1, 1, 0);
    }
    {
        GemmSK gs;
        for (int i = 0; i < 2; i++) {
            gs.A[i]  = T2 + (size_t)i * 64 * 2048;
            gs.A2[i] = nullptr;
            gs.W[i]  = out_w2 + (size_t)i * 1024 * 2048;
        }
        gemm_tc<<<dim3(8, 2, 8), 256, GSM_TOTAL>>>(gs, PART, 1024, 2048, 256, 0);
        reduce_ln<<<128, 256>>>(PART, out_b2, 1024, nullptr,
                                out_g2, out_be2, out, 1024, 8, 0, 1, nbatch);
    }
}

// round 17
// speedup vs baseline: 1.0617x; 1.0336x over previous
#include <cuda_runtime.h>
#include <math.h>
#include <stdint.h>

// ---------------------------------------------------------------------------
// BidirectionalAttentionalPromptEncoder — batch-invariant (B=1) formulation.
// R17 = R16 with the quarter-barrier base fixed (layer*512, matching 8
// releases/quarter/step * 64 steps). R16 deadlocked on a wrong base stride.
// ---------------------------------------------------------------------------

// ----------------------------- scratch --------------------------------------
#define OFF_X    0          // [4][64][1024]
#define OFF_Y0   1310720    // [4][64][1024]
#define OFF_Y1   1572864    // [4][64][1024]
#define OFF_HB   1835008    // [2][8][512]
#define OFF_GH2  2240512    // [2][64][1024]
#define OFF_BI   2633728    // [2][64][1024]
#define OFF_AO   3158016
#define OFF_LNO  3420160
#define OFF_T2   3813376    // [2][64][2048]
#define OFF_PART 4337664    // split-K partials
#define SCRATCH_TOTAL 6434816

__device__ float g_scratch[SCRATCH_TOTAL];

// quarter sub-counters: [group 0..3][quarter 0..3], each on its own 128B line;
// monotonic within a launch, zeroed by embed_kernel each launch/replay.
__device__ unsigned g_qcnt[4 * 4 * 32];

__device__ __forceinline__ float sigf(float x) { return 1.0f / (1.0f + expf(-x)); }

__device__ __forceinline__ float sig_fast(float x) {
    return 1.0f / (1.0f + __expf(-x));
}
__device__ __forceinline__ float tanh_fast(float x) {
    float e = __expf(2.0f * x);
    return 1.0f - 2.0f / (e + 1.0f);
}

__device__ __forceinline__ void bar_red_release(unsigned* cnt) {
    asm volatile("red.release.gpu.global.add.u32 [%0], %1;"
                 :: "l"(cnt), "r"(1u) : "memory");
}
__device__ __forceinline__ unsigned ld_acquire(unsigned* p) {
    unsigned v;
    asm volatile("ld.acquire.gpu.global.u32 %0, [%1];"
                 : "=r"(v) : "l"(p) : "memory");
    return v;
}
__device__ __forceinline__ uint32_t f2tf32(float x) {
    uint32_t r; asm("cvt.rna.tf32.f32 %0, %1;" : "=r"(r) : "f"(x)); return r;
}
__device__ __forceinline__ void cpasync16(void* dst, const void* src) {
    uint32_t d = (uint32_t)__cvta_generic_to_shared(dst);
    asm volatile("cp.async.ca.shared.global [%0], [%1], 16;" :: "r"(d), "l"(src));
}

// ----------------------------- embedding ------------------------------------
__global__ void embed_kernel(const float* __restrict__ pre,
                             const float* __restrict__ suf) {
    if (blockIdx.x == 0 && threadIdx.x < 16) g_qcnt[threadIdx.x * 32] = 0;
    int idx = blockIdx.x * 256 + threadIdx.x;   // < 4*64*1024
    int b = idx >> 16;
    int t = (idx >> 10) & 63;
    int c = idx & 1023;
    int st = (b >= 2) ? (63 - t) : t;
    const float* e = (b & 1) ? suf : pre;
    int i2 = c & ~1;
    const float LOG2_10000 = 13.28771237954945f;
    float divf = exp2f(-LOG2_10000 * (float)i2 * (1.0f / 1024.0f));
    double ang = (double)st * (double)divf;
    const double TWO_PI = 6.283185307179586476925286766559;
    double red = ang - floor(ang * (1.0 / TWO_PI)) * TWO_PI;
    float rf = (float)red;
    float pe = (c & 1) ? cosf(rf) : sinf(rf);
    g_scratch[OFF_X + idx] = e[st * 1024 + c] + pe;
}

// --------------------------- tf32 tensor GEMM (pipelined) -------------------
struct GemmSK {
    const float* A[8];
    const float* A2[8];
    const float* W[8];
};

#define GSTAGES 3
#define GSM_A  (64 * 36)
#define GSM_W  (128 * 36)
#define GSM_TOTAL ((GSTAGES * (GSM_A + GSM_W)) * 4)   // 82944 bytes

__global__ void __launch_bounds__(256, 2) gemm_tc(GemmSK p, float* part,
                                                  int N, int K, int chunkK,
                                                  int gather) {
    extern __shared__ float gsm[];
    float* As = gsm;
    float* Ws = gsm + GSTAGES * GSM_A;
    int bz = blockIdx.y, kc = blockIdx.z;
    const float* A  = p.A[bz];
    const float* A2 = p.A2[bz];
    const float* W  = p.W[bz];
    int n0 = blockIdx.x * 128;
    int tid = threadIdx.x;
    int warp = tid >> 5, lane = tid & 31;
    int mw = warp & 1, nw = warp >> 1;
    int gid = lane >> 2, tig = lane & 3;

    float c[2][4][4];
#pragma unroll
    for (int mt = 0; mt < 2; mt++)
#pragma unroll
        for (int nf = 0; nf < 4; nf++)
#pragma unroll
            for (int j = 0; j < 4; j++) c[mt][nf][j] = 0.0f;

    int kbeg = kc * chunkK;
    int niter = chunkK >> 5;

#define G_LOAD(K0, S)                                                          \
    do {                                                                       \
        int k0_ = (K0);                                                        \
        _Pragma("unroll")                                                      \
        for (int l = 0; l < 2; l++) {   /* A: 64x32 */                         \
            int ix = tid * 2 + l;                                              \
            int row = ix >> 3, kq = (ix & 7) * 4;                              \
            const float* asrc_;                                                \
            if (gather) {                                                      \
                if (k0_ < 1024) asrc_ = A  + (size_t)row * 1024 + k0_ + kq;    \
                else            asrc_ = A2 + (size_t)(63 - row) * 1024 + (k0_ - 1024) + kq; \
            } else {                                                           \
                asrc_ = A + (size_t)row * K + k0_ + kq;                        \
            }                                                                  \
            cpasync16(As + ((S) * 64 + row) * 36 + kq, asrc_);                 \
        }                                                                      \
        _Pragma("unroll")                                                      \
        for (int l = 0; l < 4; l++) {   /* W: 128x32 */                        \
            int ix = tid * 4 + l;                                              \
            int row = ix >> 3, kq = (ix & 7) * 4;                              \
            cpasync16(Ws + ((S) * 128 + row) * 36 + kq,                        \
                      W + (size_t)(n0 + row) * K + k0_ + kq);                  \
        }                                                                      \
    } while (0)

#pragma unroll
    for (int s = 0; s < GSTAGES - 1; s++) {
        if (s < niter) G_LOAD(kbeg + s * 32, s);
        asm volatile("cp.async.commit_group;");
    }

    for (int i = 0; i < niter; i++) {
        asm volatile("cp.async.wait_group 1;");
        __syncthreads();
        int nx = i + GSTAGES - 1;
        int nxbuf = nx % GSTAGES;
        if (nx < niter) G_LOAD(kbeg + nx * 32, nxbuf);
        asm volatile("cp.async.commit_group;");

        int buf = i % GSTAGES;
        const float* Ab = As + buf * GSM_A;
        const float* Wb = Ws + buf * GSM_W;
#pragma unroll
        for (int ks = 0; ks < 4; ks++) {
            int kb = ks * 8;
            uint32_t af[2][4];
#pragma unroll
            for (int mt = 0; mt < 2; mt++) {
                int m0 = mw * 32 + mt * 16;
                af[mt][0] = f2tf32(Ab[(m0 + gid) * 36 + kb + tig]);
                af[mt][1] = f2tf32(Ab[(m0 + gid + 8) * 36 + kb + tig]);
                af[mt][2] = f2tf32(Ab[(m0 + gid) * 36 + kb + tig + 4]);
                af[mt][3] = f2tf32(Ab[(m0 + gid + 8) * 36 + kb + tig + 4]);
            }
#pragma unroll
            for (int nf = 0; nf < 4; nf++) {
                int nrow = nw * 32 + nf * 8 + gid;
                uint32_t b0 = f2tf32(Wb[nrow * 36 + kb + tig]);
                uint32_t b1 = f2tf32(Wb[nrow * 36 + kb + tig + 4]);
#pragma unroll
                for (int mt = 0; mt < 2; mt++) {
                    asm volatile(
                        "mma.sync.aligned.m16n8k8.row.col.f32.tf32.tf32.f32 "
                        "{%0,%1,%2,%3}, {%4,%5,%6,%7}, {%8,%9}, {%0,%1,%2,%3};"
                        : "+f"(c[mt][nf][0]), "+f"(c[mt][nf][1]),
                          "+f"(c[mt][nf][2]), "+f"(c[mt][nf][3])
                        : "r"(af[mt][0]), "r"(af[mt][1]),
                          "r"(af[mt][2]), "r"(af[mt][3]), "r"(b0), "r"(b1));
                }
            }
        }
    }
#undef G_LOAD

    float* outp = part + (size_t)(kc * gridDim.y + bz) * 64 * N;
#pragma unroll
    for (int mt = 0; mt < 2; mt++) {
        int m0 = mw * 32 + mt * 16 + gid;
#pragma unroll
        for (int nf = 0; nf < 4; nf++) {
            int n = n0 + nw * 32 + nf * 8 + tig * 2;
            *(float2*)(outp + (size_t)m0 * N + n) =
                make_float2(c[mt][nf][0], c[mt][nf][1]);
            *(float2*)(outp + (size_t)(m0 + 8) * N + n) =
                make_float2(c[mt][nf][2], c[mt][nf][3]);
        }
    }
}

// --------------- fused split-K reduce + bias + LN(+gelu)(+add)(+bcast) ------
__global__ void __launch_bounds__(256) reduce_ln(
    const float* __restrict__ part, const float* __restrict__ bias, int bstride,
    const float* __restrict__ addrow,
    const float* __restrict__ gamma, const float* __restrict__ beta,
    float* __restrict__ out, int N, int KS, int dogelu, int perhalf,
    int bcast) {
    int row = blockIdx.x;
    int bz = row >> 6, m = row & 63;
    int tid = threadIdx.x;
    int nch = N >> 8;
    const float* prow = part + ((size_t)bz * 64 + m) * N;
    size_t stride = (size_t)2 * 64 * N;
    float v[8];
    float s = 0.f;
    for (int c = 0; c < nch; c++) {
        int i = c * 256 + tid;
        float acc = bias[bz * bstride + i];
        for (int ks = 0; ks < KS; ks++) acc += prow[(size_t)ks * stride + i];
        if (addrow) acc += addrow[(size_t)row * N + i];
        v[c] = acc; s += acc;
    }
    __shared__ float red[256];
    red[tid] = s; __syncthreads();
    for (int o = 128; o > 0; o >>= 1) { if (tid < o) red[tid] += red[tid + o]; __syncthreads(); }
    float mean = red[0] / N;
    __syncthreads();
    float v2 = 0.f;
    for (int c = 0; c < nch; c++) { float d = v[c] - mean; v2 += d * d; }
    red[tid] = v2; __syncthreads();
    for (int o = 128; o > 0; o >>= 1) { if (tid < o) red[tid] += red[tid + o]; __syncthreads(); }
    float inv = rsqrtf(red[0] / N + 1e-5f);
    int goff = perhalf ? bz * N : 0;
    for (int c = 0; c < nch; c++) {
        int i = c * 256 + tid;
        float o2 = (v[c] - mean) * inv * gamma[goff + i] + beta[goff + i];
        if (dogelu) o2 = 0.5f * o2 * (1.0f + erff(o2 * 0.70710678118654752f));
        if (bcast) {
            size_t basep = ((size_t)bz * bcast) * 65536 + (size_t)m * 1024 + i;
            for (int b = 0; b < bcast; b++)
                out[basep + (size_t)b * 65536] = o2;
        } else {
            out[(size_t)row * N + i] = o2;
        }
    }
}

// ------------- fused split-K reduce + bias + sigmoid gate combine -----------
__global__ void reduce_combine(const float* __restrict__ part,
                               const float* __restrict__ gate_b2, int KS) {
    int idx = blockIdx.x * 256 + threadIdx.x;   // < 2*64*1024
    int i = idx >> 16;
    int t = (idx >> 10) & 63;
    int c = idx & 1023;
    const float* prow = part + ((size_t)i * 64 + t) * 2048;
    size_t stride = (size_t)2 * 64 * 2048;
    float fs = gate_b2[i * 2048 + c];
    float bs = gate_b2[i * 2048 + 1024 + c];
    for (int ks = 0; ks < KS; ks++) {
        fs += prow[(size_t)ks * stride + c];
        bs += prow[(size_t)ks * stride + 1024 + c];
    }
    const float* Y1 = g_scratch + OFF_Y1;
    float f = Y1[(size_t)(i * 64 + t) * 1024 + c];
    float b = Y1[(size_t)((i + 2) * 64 + (63 - t)) * 1024 + c];
    g_scratch[OFF_BI + idx] = sigf(fs) * f + sigf(bs) * b;
}

// ------------------------ persistent LSTM layer ------------------------------
// 128 CTAs (1/SM). Weights + XZ slice in SMEM; lower K-half of weights in
// registers. Sync: 4 quarter sub-counters per group (8 CTAs each); warp0
// releases to its quarter after gates; warp1 lanes 0-3 poll all 4 quarters in
// parallel. Per layer each quarter gains 8*64 = 512 => base = layer*512.
__global__ void __launch_bounds__(256, 1) lstm_persistent(
    const float* __restrict__ Whh, const float* __restrict__ part,
    const float* __restrict__ bih, const float* __restrict__ bhh, int layer) {
    extern __shared__ float smem[];
    float* sw  = smem;                 // [64][516] weight rows
    float* xzs = smem + 64 * 516;      // [2][64][64]

    float* Hb = g_scratch + OFF_HB;
    float* Y  = g_scratch + (layer == 0 ? OFF_Y0 : OFF_Y1);

    int blk = blockIdx.x;
    int g = blk >> 5;                  // lstm*2+dir
    int chunk = blk & 31;
    int lstm = g >> 1, dir = g & 1;
    int scanA = lstm * 4 + dir;
    int scanB = lstm * 4 + 2 + dir;
    int u0 = chunk * 16;
    int wi = (lstm * 2 + layer) * 2 + dir;
    const float* Wg   = Whh + (size_t)wi * (2048 * 512);
    const float* bihg = bih + (size_t)wi * 2048;
    const float* bhhg = bhh + (size_t)wi * 2048;
    int tid = threadIdx.x;
    unsigned* myq = &g_qcnt[(g * 4 + (chunk >> 3)) * 32];
    unsigned base = (unsigned)layer * 512u;    // 8 CTAs/quarter * 64 releases

    for (int i4 = tid; i4 < 8192; i4 += 256) {
        int r = i4 >> 7, c4 = i4 & 127;
        int grow = (r >> 4) * 512 + u0 + (r & 15);
        float4 v = *(const float4*)(Wg + (size_t)grow * 512 + c4 * 4);
        *(float4*)(sw + r * 516 + c4 * 4) = v;
    }
    for (int i = tid; i < 8192; i += 256) {
        int sB = i >> 12, t = (i >> 6) & 63, r = i & 63;
        int scan = sB ? scanB : scanA;
        int row = (r >> 4) * 512 + u0 + (r & 15);
        size_t e0 = ((size_t)(0 * 8 + scan) * 64 + t) * 2048 + row;
        size_t e1 = ((size_t)(1 * 8 + scan) * 64 + t) * 2048 + row;
        xzs[i] = part[e0] + part[e1] + bihg[row] + bhhg[row];
    }
    if (tid < 32) {
        int sB = tid >> 4, uu = tid & 15;
        int scan = sB ? scanB : scanA;
        Hb[scan * 512 + u0 + uu] = 0.f;
    }
    __syncthreads();
    if (tid == 0) bar_red_release(myq);
    if (tid >= 32 && tid < 36) {
        unsigned* q = &g_qcnt[(g * 4 + (tid - 32)) * 32];
        while (ld_acquire(q) < base + 8u) {}
    }
    __syncthreads();

    __shared__ __align__(16) float hA[512], hB[512];
    __shared__ float part_s[2][4][64];

    // preload h for step 0
    {
        int q = tid & 127;
        const float* src = Hb + (tid < 128 ? scanA : scanB) * 512;
        float4 v = __ldcg((const float4*)src + q);
        float* dst = (tid < 128) ? hA : hB;
        *(float4*)(dst + q * 4) = v;
    }
    __syncthreads();

    int r = tid & 63, pp = tid >> 6;
    float4 wreg[16];
    {
        const float4* wsrc = (const float4*)(sw + r * 516 + pp * 128);
#pragma unroll
        for (int k = 0; k < 16; k++) wreg[k] = wsrc[k];
    }
    const float4* wr = (const float4*)(sw + r * 516 + pp * 128);

    float cstate = 0.f;
    int mySB = tid >> 4, myU = tid & 15;
    int myScan = mySB ? scanB : scanA;

    for (int j = 0; j < 64; j++) {
        int t = dir ? (63 - j) : j;
        {
            const float4* a4 = (const float4*)(hA + pp * 128);
            const float4* b4 = (const float4*)(hB + pp * 128);
            float accA = 0.f, accB = 0.f;
#pragma unroll
            for (int i = 0; i < 16; i++) {          // register half (k 0..63)
                float4 w = wreg[i], a = a4[i], b = b4[i];
                accA += w.x * a.x + w.y * a.y + w.z * a.z + w.w * a.w;
                accB += w.x * b.x + w.y * b.y + w.z * b.z + w.w * b.w;
            }
#pragma unroll
            for (int i = 16; i < 32; i++) {         // smem half (k 64..127)
                float4 w = wr[i], a = a4[i], b = b4[i];
                accA += w.x * a.x + w.y * a.y + w.z * a.z + w.w * a.w;
                accB += w.x * b.x + w.y * b.y + w.z * b.z + w.w * b.w;
            }
            part_s[0][pp][r] = accA;
            part_s[1][pp][r] = accB;
        }
        __syncthreads();
        float* Hnext = Hb + ((j + 1) & 1) * 4096;
        if (tid < 32) {
            float z[4];
#pragma unroll
            for (int gg = 0; gg < 4; gg++) {
                int rr = gg * 16 + myU;
                z[gg] = xzs[mySB * 4096 + t * 64 + rr]
                      + part_s[mySB][0][rr] + part_s[mySB][1][rr]
                      + part_s[mySB][2][rr] + part_s[mySB][3][rr];
            }
            float c = sig_fast(z[1]) * cstate + sig_fast(z[0]) * tanh_fast(z[2]);
            float h = sig_fast(z[3]) * tanh_fast(c);
            cstate = c;
            Hnext[myScan * 512 + u0 + myU] = h;
            int seq = lstm * 2 + mySB;
            Y[(size_t)(seq * 64 + t) * 1024 + dir * 512 + u0 + myU] = h;
            __syncwarp(0xffffffffu);               // order warp0's STGs
            if (tid == 0 && j < 63) bar_red_release(myq);
        } else if (tid >= 32 && tid < 36 && j < 63) {
            // 4 lanes poll the 4 quarter counters in parallel
            unsigned tgt = base + (unsigned)(j + 2) * 8u;
            unsigned* q = &g_qcnt[(g * 4 + (tid - 32)) * 32];
            while (ld_acquire(q) < tgt) {}
        }
        if (j == 63) break;
        __syncthreads();
        {
            const float* Hp = Hb + ((j + 1) & 1) * 4096;
            int q = tid & 127;
            const float* src = Hp + (tid < 128 ? scanA : scanB) * 512;
            float4 v = __ldcg((const float4*)src + q);
            float* dst = (tid < 128) ? hA : hB;
            *(float4*)(dst + q * 4) = v;
        }
        __syncthreads();
    }
}

// ----------------------------- attention core -------------------------------
__global__ void __launch_bounds__(256) attn_core_kernel(
    const float* __restrict__ part, const float* __restrict__ attn_b) {
    extern __shared__ float asm_[];
    float* KV  = asm_;            // [64][128]
    float* Qs  = asm_ + 8192;     // [64][128]
    float* Ssm = asm_ + 16384;    // [64][64]
    const int h = blockIdx.x;
    const int a = blockIdx.y;
    float* AO = g_scratch + OFF_AO + (size_t)a * 64 * 1024;
    int tid = threadIdx.x;

    for (int i = tid; i < 64 * 128; i += 256) {
        int m = i >> 7, d = i & 127;
        int col = h * 128 + d;
        int eq = a * 3 + 0, ek = a * 3 + 1;
        float q = 0.f, k = 0.f;
#pragma unroll
        for (int ks = 0; ks < 4; ks++) {
            q += part[((size_t)(ks * 6 + eq) * 64 + m) * 1024 + col];
            k += part[((size_t)(ks * 6 + ek) * 64 + m) * 1024 + col];
        }
        q += attn_b[(a * 4 + 0) * 1024 + col];
        k += attn_b[(a * 4 + 1) * 1024 + col];
        Qs[m * 128 + d] = q;
        KV[m * 128 + d] = k;
    }
    __syncthreads();
    {
        int n = tid >> 2, p = tid & 3;
        float acc[16];
#pragma unroll
        for (int i = 0; i < 16; i++) acc[i] = 0.f;
        const float* q = Qs + n * 128;
        for (int d = 0; d < 128; d++) {
            float qv = q[d];
#pragma unroll
            for (int i = 0; i < 16; i++) acc[i] += qv * KV[(p * 16 + i) * 128 + d];
        }
        const float scale = 0.08838834764831845f;
#pragma unroll
        for (int i = 0; i < 16; i++) Ssm[n * 64 + p * 16 + i] = acc[i] * scale;
    }
    __syncthreads();
    for (int i = tid; i < 64 * 128; i += 256) {
        int m = i >> 7, d = i & 127;
        int col = h * 128 + d;
        int ev = a * 3 + 2;
        float v = 0.f;
#pragma unroll
        for (int ks = 0; ks < 4; ks++)
            v += part[((size_t)(ks * 6 + ev) * 64 + m) * 1024 + col];
        v += attn_b[(a * 4 + 2) * 1024 + col];
        KV[m * 128 + d] = v;
    }
    if (tid < 64) {
        float mx = -1e30f;
        for (int m = 0; m < 64; m++) mx = fmaxf(mx, Ssm[tid * 64 + m]);
        float sum = 0.f;
        for (int m = 0; m < 64; m++) {
            float e = expf(Ssm[tid * 64 + m] - mx);
            Ssm[tid * 64 + m] = e; sum += e;
        }
        float invs = 1.f / sum;
        for (int m = 0; m < 64; m++) Ssm[tid * 64 + m] *= invs;
    }
    __syncthreads();
    {
        int n = tid >> 2, p = tid & 3;
        float acc[32];
#pragma unroll
        for (int i = 0; i < 32; i++) acc[i] = 0.f;
        for (int m = 0; m < 64; m++) {
            float w = Ssm[n * 64 + m];
#pragma unroll
            for (int i = 0; i < 32; i++) acc[i] += w * KV[m * 128 + p * 32 + i];
        }
        for (int i = 0; i < 32; i++)
            AO[n * 1024 + h * 128 + p * 32 + i] = acc[i];
    }
}

// ------------------------------- launcher -----------------------------------
extern "C" void kernel_launch(void* const* d_in, const int* in_sizes, int n_in,
                              void* d_out, int out_size) {
    const float* prefix  = (const float*)d_in[0];
    const float* suffix  = (const float*)d_in[1];
    const float* Wih     = (const float*)d_in[2];
    const float* Whh     = (const float*)d_in[3];
    const float* bih     = (const float*)d_in[4];
    const float* bhh     = (const float*)d_in[5];
    const float* attn_w  = (const float*)d_in[6];
    const float* attn_b  = (const float*)d_in[7];
    const float* gate_w1 = (const float*)d_in[8];
    const float* gate_b1 = (const float*)d_in[9];
    const float* gate_lg = (const float*)d_in[10];
    const float* gate_lb = (const float*)d_in[11];
    const float* gate_w2 = (const float*)d_in[12];
    const float* gate_b2 = (const float*)d_in[13];
    const float* out_w1  = (const float*)d_in[14];
    const float* out_b1  = (const float*)d_in[15];
    const float* out_g1  = (const float*)d_in[16];
    const float* out_be1 = (const float*)d_in[17];
    const float* out_w2  = (const float*)d_in[18];
    const float* out_b2  = (const float*)d_in[19];
    const float* out_g2  = (const float*)d_in[20];
    const float* out_be2 = (const float*)d_in[21];
    const float* ln_g    = (const float*)d_in[22];
    const float* ln_b    = (const float*)d_in[23];
    float* out = (float*)d_out;

    float* S = nullptr;
    cudaGetSymbolAddress((void**)&S, g_scratch);
    float* X    = S + OFF_X;
    float* Y0   = S + OFF_Y0;
    float* Y1   = S + OFF_Y1;
    float* GH2  = S + OFF_GH2;
    float* BI   = S + OFF_BI;
    float* AO   = S + OFF_AO;
    float* LNO  = S + OFF_LNO;
    float* T2   = S + OFF_T2;
    float* PART = S + OFF_PART;

    const int LSTM_SMEM = (64 * 516 + 8192) * 4;
    const int ATTN_SMEM = (8192 + 8192 + 4096) * 4;
    static int smem_set = 0;
    if (!smem_set) {
        cudaFuncSetAttribute(lstm_persistent,
                             cudaFuncAttributeMaxDynamicSharedMemorySize, LSTM_SMEM);
        cudaFuncSetAttribute(gemm_tc,
                             cudaFuncAttributeMaxDynamicSharedMemorySize, GSM_TOTAL);
        cudaFuncSetAttribute(attn_core_kernel,
                             cudaFuncAttributeMaxDynamicSharedMemorySize, ATTN_SMEM);
        smem_set = 1;
    }

    int nbatch = (out_size / 2) / 65536;   // 64

    // 1) embed + PE (zeroes quarter counters)
    embed_kernel<<<1024, 256>>>(prefix, suffix);

    // 2) bilstm: XZ gemm (split-K, KS=2) -> persistent LSTM (reduce fused in)
    for (int layer = 0; layer < 2; layer++) {
        const float* src = (layer == 0) ? X : Y0;
        GemmSK gs;
        for (int s = 0; s < 8; s++) {
            int seq = s >> 1, dir = s & 1, lstm = seq >> 1;
            int wi = (lstm * 2 + layer) * 2 + dir;
            gs.A[s]  = src + (size_t)seq * 64 * 1024;
            gs.A2[s] = nullptr;
            gs.W[s]  = Wih + (size_t)wi * 2048 * 1024;
        }
        gemm_tc<<<dim3(16, 8, 2), 256, GSM_TOTAL>>>(gs, PART, 2048, 1024, 512, 0);
        lstm_persistent<<<128, 256, LSTM_SMEM>>>(Whh, PART, bih, bhh, layer);
    }

    // 3) gates: GEMM1 gathers concat(Y1[i], flip(Y1[i+2])) directly; KS=8
    {
        GemmSK gs;
        for (int i = 0; i < 2; i++) {
            gs.A[i]  = Y1 + (size_t)i * 64 * 1024;
            gs.A2[i] = Y1 + (size_t)(i + 2) * 64 * 1024;
            gs.W[i]  = gate_w1 + (size_t)i * 1024 * 2048;
        }
        gemm_tc<<<dim3(8, 2, 8), 256, GSM_TOTAL>>>(gs, PART, 1024, 2048, 256, 1);
        reduce_ln<<<128, 256>>>(PART, gate_b1, 1024, nullptr,
                                gate_lg, gate_lb, GH2, 1024, 8, 1, 1, 0);
    }
    {
        GemmSK gs;
        for (int i = 0; i < 2; i++) {
            gs.A[i]  = GH2 + (size_t)i * 64 * 1024;
            gs.A2[i] = nullptr;
            gs.W[i]  = gate_w2 + (size_t)i * 2048 * 1024;
        }
        gemm_tc<<<dim3(16, 2, 8), 256, GSM_TOTAL>>>(gs, PART, 2048, 1024, 128, 0);
        reduce_combine<<<512, 256>>>(PART, gate_b2, 8);
    }

    // 4) cross attention: QKV gemm (KS=4) -> fused attn core -> out proj
    {
        GemmSK gs;
        for (int a = 0; a < 2; a++)
            for (int k3 = 0; k3 < 3; k3++) {
                int e = a * 3 + k3;
                int srcIdx = (k3 == 0) ? a : (1 - a);
                gs.A[e]  = BI + (size_t)srcIdx * 64 * 1024;
                gs.A2[e] = nullptr;
                gs.W[e]  = attn_w + (size_t)(a * 4 + k3) * 1024 * 1024;
            }
        gemm_tc<<<dim3(8, 6, 4), 256, GSM_TOTAL>>>(gs, PART, 1024, 1024, 256, 0);
        attn_core_kernel<<<dim3(8, 2), 256, ATTN_SMEM>>>(PART, attn_b);
    }
    {
        GemmSK gs;
        for (int a = 0; a < 2; a++) {
            gs.A[a]  = AO + (size_t)a * 64 * 1024;
            gs.A2[a] = nullptr;
            gs.W[a]  = attn_w + (size_t)(a * 4 + 3) * 1024 * 1024;
        }
        gemm_tc<<<dim3(8, 2, 8), 256, GSM_TOTAL>>>(gs, PART, 1024, 1024, 128, 0);
        reduce_ln<<<128, 256>>>(PART, attn_b + 3 * 1024, 4096, BI,
                                ln_g, ln_b, LNO, 1024, 8, 0, 0, 0);
    }

    // 5) output transforms
    {
        GemmSK gs;
        for (int i = 0; i < 2; i++) {
            gs.A[i]  = LNO + (size_t)i * 64 * 1024;
            gs.A2[i] = nullptr;
            gs.W[i]  = out_w1 + (size_t)i * 2048 * 1024;
        }
        gemm_tc<<<dim3(16, 2, 8), 256, GSM_TOTAL>>>(gs, PART, 2048, 1024, 128, 0);
        reduce_ln<<<128, 256>>>(PART, out_b1, 2048, nullptr,
                                out_g1, out_be1, T2, 2048, 8, 1, 1, 0);
    }
    {
        GemmSK gs;
        for (int i = 0; i < 2; i++) {
            gs.A[i]  = T2 + (size_t)i * 64 * 2048;
            gs.A2[i] = nullptr;
            gs.W[i]  = out_w2 + (size_t)i * 1024 * 2048;
        }
        gemm_tc<<<dim3(8, 2, 8), 256, GSM_TOTAL>>>(gs, PART, 1024, 2048, 256, 0);
        reduce_ln<<<128, 256>>>(PART, out_b2, 1024, nullptr,
                                out_g2, out_be2, out, 1024, 8, 0, 1, nbatch);
    }
}